// round 13
// baseline (speedup 1.0000x reference)
#include <cuda_runtime.h>
#include <cuda_bf16.h>
#include <math.h>
#include <stdint.h>

// ---------------- problem constants ----------------
#define BB 2
#define TT 2048
#define DD 1024
#define HH 16
#define DH 64
#define RR 8
#define BT (BB*TT)            // 4096 tokens
typedef __nv_bfloat16 bf16;

// ================= low-level helpers (baseline PTX ISA only) =================
__device__ __forceinline__ uint32_t smem_u32(const void* p) {
    uint32_t a;
    asm("{ .reg .u64 t; cvta.to.shared.u64 t, %1; cvt.u32.u64 %0, t; }" : "=r"(a) : "l"(p));
    return a;
}
__device__ __forceinline__ void ldsm_x4(uint32_t* r, uint32_t addr) {
    asm volatile("ldmatrix.sync.aligned.m8n8.x4.shared.b16 {%0,%1,%2,%3}, [%4];"
        : "=r"(r[0]), "=r"(r[1]), "=r"(r[2]), "=r"(r[3]) : "r"(addr));
}
__device__ __forceinline__ void mma_bf16(float* d, const uint32_t* a, const uint32_t* b) {
    asm volatile(
        "mma.sync.aligned.m16n8k16.row.col.f32.bf16.bf16.f32 "
        "{%0,%1,%2,%3}, {%4,%5,%6,%7}, {%8,%9}, {%0,%1,%2,%3};"
        : "+f"(d[0]), "+f"(d[1]), "+f"(d[2]), "+f"(d[3])
        : "r"(a[0]), "r"(a[1]), "r"(a[2]), "r"(a[3]), "r"(b[0]), "r"(b[1]));
}
__device__ __forceinline__ void cp16(uint32_t dst, const void* src) {
    asm volatile("cp.async.cg.shared.global [%0], [%1], 16;" :: "r"(dst), "l"(src));
}
#define CP_COMMIT() asm volatile("cp.async.commit_group;" ::: "memory")
#define CP_WAIT1()  asm volatile("cp.async.wait_group 1;" ::: "memory")
#define CP_WAIT0()  asm volatile("cp.async.wait_group 0;" ::: "memory")
#define SWZ128(off) ((off) ^ (((off) >> 3) & 0x70))
#define SWZ64(off)  ((off) ^ (((off) >> 3) & 0x30))

__device__ __forceinline__ void split2(float x, float y, uint32_t& h, uint32_t& l) {
    bf16 hx = __float2bfloat16(x), hy = __float2bfloat16(y);
    bf16 lx = __float2bfloat16(x - __bfloat162float(hx));
    bf16 ly = __float2bfloat16(y - __bfloat162float(hy));
    __nv_bfloat162 hp = __halves2bfloat162(hx, hy);
    __nv_bfloat162 lp = __halves2bfloat162(lx, ly);
    h = *(uint32_t*)&hp; l = *(uint32_t*)&lp;
}

// ---------------- scratch (__device__ globals; alloc-free) ----------------
__device__ __align__(256) bf16 g_qWh[DD*DD],  g_qWl[DD*DD];
__device__ __align__(256) bf16 g_kWh[DD*DD],  g_kWl[DD*DD];
__device__ __align__(256) bf16 g_vWh[DD*DD],  g_vWl[DD*DD];
__device__ __align__(256) bf16 g_fWh[DD*DD],  g_fWl[DD*DD];
__device__ __align__(256) bf16 g_w1h[4*DD*DD], g_w1l[4*DD*DD];
__device__ __align__(256) bf16 g_w2h[2*DD*DD], g_w2l[2*DD*DD];
__device__ __align__(256) bf16 g_Yh[BT*DD],  g_Yl[BT*DD];
__device__ __align__(256) bf16 g_Qh[BT*DD],  g_Ql[BT*DD];
__device__ __align__(256) bf16 g_Kh[BT*DD],  g_Kl[BT*DD];
__device__ __align__(256) bf16 g_Vth[BT*DD], g_Vtl[BT*DD];   // [B][D][T]
__device__ __align__(256) bf16 g_Oh[BT*DD],  g_Ol[BT*DD];
__device__ __align__(256) bf16 g_Hfh[BT*4*DD], g_Hfl[BT*4*DD];
__device__ __align__(256) bf16 g_Gh[BT*2*DD],  g_Gl[BT*2*DD];
__device__ __align__(256) float g_X1[BT*DD];
__device__ unsigned char g_flags[BB*16];

// ================= HMMA split-bf16 GEMM =================
// BK=32 (64-byte rows, SW64 swizzle), 2 stages -> 67.6 KB smem -> 2 CTAs/SM.
// C[m,n] = sum_k A[m,k]*B[n,k]. 256 threads; BM=128; warp grid 4x2, warp tile 32x(BN/2).
// EPI: 0 = fp32 out (+optional Res), 1 = split bf16 out, 2 = split bf16 TRANSPOSED out.
template<int BN, int EPI>
__global__ void __launch_bounds__(256, 2)
tc_gemm(const bf16* __restrict__ Ah, const bf16* __restrict__ Al,
        const bf16* __restrict__ Bh, const bf16* __restrict__ Bl,
        float* __restrict__ C, const float* __restrict__ Res,
        bf16* __restrict__ Ch, bf16* __restrict__ Cl,
        int K, int lda, int ldb, int ldc, int zdiv,
        long long sA1, long long sA2, long long sB1, long long sB2,
        long long sC1, long long sC2)
{
    constexpr int WTN  = BN / 2;
    constexpr int NB8  = WTN / 8;
    constexpr int A_HI = 0;           // stage-relative offsets (bytes), BK=32 rows of 64B
    constexpr int A_LO = 8192;
    constexpr int B_HI = 16384;
    constexpr int B_LO = 16384 + BN * 64;
    constexpr int STAGE = 16384 + BN * 128;   // 32768 for BN=128

    extern __shared__ __align__(128) char smem[];
    uint32_t sb = smem_u32(smem);
    int tid = threadIdx.x, wid = tid >> 5, lane = tid & 31;
    int wm = wid & 3, wn = wid >> 2;

    int z = blockIdx.z, z1 = z / zdiv, z2 = z - z1 * zdiv;
    long long aoff = z1 * sA1 + z2 * sA2;
    long long boff = z1 * sB1 + z2 * sB2;
    long long coff = z1 * sC1 + z2 * sC2;
    Ah += aoff; Al += aoff; Bh += boff; Bl += boff;
    if (EPI == 0) { C += coff; if (Res) Res += coff; }
    else          { Ch += coff; Cl += coff; }
    int bm = blockIdx.y * 128;
    int bn = blockIdx.x * BN;

    float acc[2][NB8][4];
#pragma unroll
    for (int mt = 0; mt < 2; mt++)
#pragma unroll
        for (int nb = 0; nb < NB8; nb++)
#pragma unroll
            for (int i = 0; i < 4; i++) acc[mt][nb][i] = 0.f;

    const int NC = K >> 5;

    // ---- async copy of one 32-k chunk into stage s ----
    // A: 128 rows x 4 groups-of-16B = 512 -> 2 iters * 256 threads. B: BN*4/256 iters.
    auto issue_chunk = [&](int c, int s) {
        int k0 = c << 5;
        uint32_t st = sb + s * STAGE;
#pragma unroll
        for (int it = 0; it < 2; it++) {
            int idx = it * 256 + tid;
            int row = idx >> 2, g16 = idx & 3;
            long long g = (long long)(bm + row) * lda + k0 + g16 * 8;
            uint32_t so = SWZ64((uint32_t)(row * 64 + g16 * 16));
            cp16(st + A_HI + so, Ah + g);
            cp16(st + A_LO + so, Al + g);
        }
#pragma unroll
        for (int it = 0; it < BN / 64; it++) {
            int idx = it * 256 + tid;
            int row = idx >> 2, g16 = idx & 3;
            long long g = (long long)(bn + row) * ldb + k0 + g16 * 8;
            uint32_t so = SWZ64((uint32_t)(row * 64 + g16 * 16));
            cp16(st + B_HI + so, Bh + g);
            cp16(st + B_LO + so, Bl + g);
        }
        CP_COMMIT();
    };

    issue_chunk(0, 0);

    for (int c = 0; c < NC; c++) {
        if (c + 1 < NC) { issue_chunk(c + 1, (c + 1) & 1); CP_WAIT1(); }
        else            { CP_WAIT0(); }
        __syncthreads();

        uint32_t st = sb + (c & 1) * STAGE;
#pragma unroll
        for (int j = 0; j < 2; j++) {
            // A fragments (two m16 tiles, hi + lo)
            uint32_t aH[2][4], aL[2][4];
#pragma unroll
            for (int mt = 0; mt < 2; mt++) {
                int row = wm * 32 + mt * 16 + (lane & 15);
                int gr  = j * 2 + (lane >> 4);
                uint32_t so = SWZ64((uint32_t)(row * 64 + gr * 16));
                ldsm_x4(aH[mt], st + A_HI + so);
                ldsm_x4(aL[mt], st + A_LO + so);
            }
            // B tiles in transient pairs to bound register pressure
#pragma unroll
            for (int nbp = 0; nbp < NB8 / 2; nbp++) {
                int row = wn * WTN + (nbp * 2 + (lane >> 4)) * 8 + (lane & 7);
                int gr  = j * 2 + ((lane >> 3) & 1);
                uint32_t so = SWZ64((uint32_t)(row * 64 + gr * 16));
                uint32_t bh4[4], bl4[4];
                ldsm_x4(bh4, st + B_HI + so);
                ldsm_x4(bl4, st + B_LO + so);
#pragma unroll
                for (int mt = 0; mt < 2; mt++) {
                    mma_bf16(acc[mt][nbp*2],     aH[mt], bh4);
                    mma_bf16(acc[mt][nbp*2],     aH[mt], bl4);
                    mma_bf16(acc[mt][nbp*2],     aL[mt], bh4);
                    mma_bf16(acc[mt][nbp*2 + 1], aH[mt], bh4 + 2);
                    mma_bf16(acc[mt][nbp*2 + 1], aH[mt], bl4 + 2);
                    mma_bf16(acc[mt][nbp*2 + 1], aL[mt], bh4 + 2);
                }
            }
        }
        __syncthreads();
    }

    // ---- epilogue: bounce accumulators through (reused) stage smem ----
    constexpr int BNP = BN + 4;
    float* sE = (float*)smem;                       // [128][BNP]
#pragma unroll
    for (int mt = 0; mt < 2; mt++)
#pragma unroll
        for (int nb = 0; nb < NB8; nb++) {
            int r0 = wm * 32 + mt * 16 + (lane >> 2);
            int c0 = wn * WTN + nb * 8 + (lane & 3) * 2;
            sE[r0 * BNP + c0]       = acc[mt][nb][0];
            sE[r0 * BNP + c0 + 1]   = acc[mt][nb][1];
            sE[(r0+8) * BNP + c0]   = acc[mt][nb][2];
            sE[(r0+8) * BNP + c0+1] = acc[mt][nb][3];
        }
    __syncthreads();

    if (EPI == 2) {
        int f = tid >> 1, seg = tid & 1;
        long long ob = (long long)(bn + f) * ldc + bm + seg * 64;
#pragma unroll
        for (int cc = 0; cc < 64; cc += 4) {
            bf16 h[4], l[4];
#pragma unroll
            for (int i = 0; i < 4; i++) {
                float v = sE[(seg * 64 + cc + i) * BNP + f];
                h[i] = __float2bfloat16(v);
                l[i] = __float2bfloat16(v - __bfloat162float(h[i]));
            }
            *(__nv_bfloat162*)(Ch + ob + cc)     = __halves2bfloat162(h[0], h[1]);
            *(__nv_bfloat162*)(Ch + ob + cc + 2) = __halves2bfloat162(h[2], h[3]);
            *(__nv_bfloat162*)(Cl + ob + cc)     = __halves2bfloat162(l[0], l[1]);
            *(__nv_bfloat162*)(Cl + ob + cc + 2) = __halves2bfloat162(l[2], l[3]);
        }
    } else {
        constexpr int NQ = BN / 4;
#pragma unroll
        for (int p = 0; p < BN / 8; p++) {
            int idx = p * 256 + tid;
            int r  = idx / NQ;
            int cq = (idx % NQ) * 4;
            float v0 = sE[r * BNP + cq + 0];
            float v1 = sE[r * BNP + cq + 1];
            float v2 = sE[r * BNP + cq + 2];
            float v3 = sE[r * BNP + cq + 3];
            long long ob = (long long)(bm + r) * ldc + bn + cq;
            if (EPI == 0) {
                if (Res) {
                    float4 rr = *(const float4*)(Res + ob);
                    v0 += rr.x; v1 += rr.y; v2 += rr.z; v3 += rr.w;
                }
                float4 o; o.x = v0; o.y = v1; o.z = v2; o.w = v3;
                *(float4*)(C + ob) = o;
            } else {
                uint32_t h0, l0, h1, l1;
                split2(v0, v1, h0, l0);
                split2(v2, v3, h1, l1);
                *(uint32_t*)(Ch + ob)     = h0;
                *(uint32_t*)(Ch + ob + 2) = h1;
                *(uint32_t*)(Cl + ob)     = l0;
                *(uint32_t*)(Cl + ob + 2) = l1;
            }
        }
    }
}

// ================= T5 bucket =================
__device__ __forceinline__ int rel_bucket(int rel)
{
    int base = (rel > 0) ? 16 : 0;
    int r = rel < 0 ? -rel : rel;
    int v;
    if      (r <  8) v = r;
    else if (r < 12) v = 8;
    else if (r < 16) v = 9;
    else if (r < 23) v = 10;
    else if (r < 32) v = 11;
    else if (r < 46) v = 12;
    else if (r < 64) v = 13;
    else if (r < 91) v = 14;
    else             v = 15;
    return base + v;
}

// ================= flash attention (fused QK^T + softmax + PV) =================
// grid (qt=16, bh=32), 256 threads, 8 warps x 16 query rows.
// smem: Q hi/lo 32KB @0; 2 stages of {K hi/lo 32KB, V hi/lo 32KB} @32768; lut @163840.
#define FA_STG   32768
#define FA_STAGE 65536
#define FA_LUT   163840
#define FA_SMEM  164992

__global__ void __launch_bounds__(256, 1)
flash_attn(const bf16* __restrict__ Qh_, const bf16* __restrict__ Ql_,
           const bf16* __restrict__ Kh_, const bf16* __restrict__ Kl_,
           const bf16* __restrict__ Vh_, const bf16* __restrict__ Vl_,
           const float* __restrict__ relb, const int* __restrict__ mask,
           const unsigned char* __restrict__ flags,
           bf16* __restrict__ Oh_, bf16* __restrict__ Ol_)
{
    extern __shared__ __align__(128) char smem[];
    uint32_t sb = smem_u32(smem);
    int tid = threadIdx.x, wid = tid >> 5, lane = tid & 31;
    int qt = blockIdx.x, bh = blockIdx.y;
    int b = bh >> 4, h = bh & (HH - 1);

    // exp(bias) LUT over clamped (j-i); exact: bucket(d) constant for |d|>=91
    float* lutF = (float*)(smem + FA_LUT);
    for (int ii = tid; ii < 257; ii += 256)
        lutF[ii] = __expf(relb[rel_bucket(ii - 128) * HH + h]);
    bool allone = flags[b * 16 + qt] != 0;

    const bf16* Qbh = Qh_ + ((long long)b * TT + qt * 128) * DD + h * DH;
    const bf16* Qbl = Ql_ + ((long long)b * TT + qt * 128) * DD + h * DH;
    const bf16* Kbh = Kh_ + (long long)b * TT * DD + h * DH;
    const bf16* Kbl = Kl_ + (long long)b * TT * DD + h * DH;
    const bf16* Vbh = Vh_ + (long long)b * DD * TT + (long long)h * DH * TT;
    const bf16* Vbl = Vl_ + (long long)b * DD * TT + (long long)h * DH * TT;

    // Q tile: 128 rows x 64 bf16 hi/lo
#pragma unroll
    for (int it = 0; it < 4; it++) {
        int idx = it * 256 + tid;
        int row = idx >> 3, g16 = idx & 7;
        long long g = (long long)row * DD + g16 * 8;
        uint32_t so = SWZ128((uint32_t)(row * 128 + g16 * 16));
        cp16(sb + so,         Qbh + g);
        cp16(sb + 16384 + so, Qbl + g);
    }
    CP_COMMIT();

    auto issue_kv = [&](int t, int s) {
        uint32_t st = sb + FA_STG + s * FA_STAGE;
#pragma unroll
        for (int it = 0; it < 4; it++) {
            int idx = it * 256 + tid;
            int row = idx >> 3, g16 = idx & 7;
            long long g = (long long)(t * 128 + row) * DD + g16 * 8;
            uint32_t so = SWZ128((uint32_t)(row * 128 + g16 * 16));
            cp16(st + so,         Kbh + g);
            cp16(st + 16384 + so, Kbl + g);
        }
#pragma unroll
        for (int it = 0; it < 4; it++) {
            int idx = it * 256 + tid;
            int chunk = idx >> 9, row = (idx >> 3) & 63, g16 = idx & 7;
            long long g = (long long)row * TT + t * 128 + chunk * 64 + g16 * 8;
            uint32_t so = (uint32_t)(chunk * 8192) + SWZ128((uint32_t)(row * 128 + g16 * 16));
            cp16(st + 32768 + so, Vbh + g);
            cp16(st + 49152 + so, Vbl + g);
        }
        CP_COMMIT();
    };
    issue_kv(0, 0);

    float Oacc[8][4];
#pragma unroll
    for (int nb = 0; nb < 8; nb++)
#pragma unroll
        for (int q = 0; q < 4; q++) Oacc[nb][q] = 0.f;
    float rs0 = 0.f, rs1 = 0.f;

    int i0 = qt * 128 + wid * 16 + (lane >> 2);      // global query pos (row r)
    const int* mrow0 = mask + (long long)b * TT * TT + (long long)i0 * TT;
    const int* mrow1 = mrow0 + 8 * TT;

    for (int t = 0; t < TT / 128; t++) {
        if (t + 1 < TT / 128) { issue_kv(t + 1, (t + 1) & 1); CP_WAIT1(); }
        else                  { CP_WAIT0(); }
        __syncthreads();
        uint32_t st = sb + FA_STG + (t & 1) * FA_STAGE;

        float acc[16][4];
#pragma unroll
        for (int nb = 0; nb < 16; nb++)
#pragma unroll
            for (int q = 0; q < 4; q++) acc[nb][q] = 0.f;

        // ---- S = Q K^T over k=64 ----
#pragma unroll
        for (int j = 0; j < 4; j++) {
            uint32_t aH[4], aL[4];
            {
                int row = wid * 16 + (lane & 15);
                int gr  = j * 2 + (lane >> 4);
                uint32_t so = SWZ128((uint32_t)(row * 128 + gr * 16));
                ldsm_x4(aH, sb + so);
                ldsm_x4(aL, sb + 16384 + so);
            }
#pragma unroll
            for (int nbp = 0; nbp < 8; nbp++) {
                int brow = (nbp * 2 + (lane >> 4)) * 8 + (lane & 7);
                int bgr  = j * 2 + ((lane >> 3) & 1);
                uint32_t bso = SWZ128((uint32_t)(brow * 128 + bgr * 16));
                uint32_t bh4[4], bl4[4];
                ldsm_x4(bh4, st + bso);
                ldsm_x4(bl4, st + 16384 + bso);
                mma_bf16(acc[nbp*2],     aH, bh4);
                mma_bf16(acc[nbp*2],     aH, bl4);
                mma_bf16(acc[nbp*2],     aL, bh4);
                mma_bf16(acc[nbp*2 + 1], aH, bh4 + 2);
                mma_bf16(acc[nbp*2 + 1], aH, bl4 + 2);
                mma_bf16(acc[nbp*2 + 1], aL, bh4 + 2);
            }
        }

        // ---- P = exp(S/8)*exp(bias)*mask (unnormalized); accumulate row sums ----
        int jb = t * 128 + (lane & 3) * 2;
#pragma unroll
        for (int nb = 0; nb < 16; nb++) {
            int j0  = jb + nb * 8;
            int d0  = j0 - i0;
            int d1  = d0 - 8;           // j0 - (i0+8)
            float e0 = __expf(acc[nb][0] * 0.125f) * lutF[min(max(d0,     -128), 128) + 128];
            float e1 = __expf(acc[nb][1] * 0.125f) * lutF[min(max(d0 + 1, -128), 128) + 128];
            float e2 = __expf(acc[nb][2] * 0.125f) * lutF[min(max(d1,     -128), 128) + 128];
            float e3 = __expf(acc[nb][3] * 0.125f) * lutF[min(max(d1 + 1, -128), 128) + 128];
            if (!allone) {
                e0 = mrow0[j0]     ? e0 : 0.f;
                e1 = mrow0[j0 + 1] ? e1 : 0.f;
                e2 = mrow1[j0]     ? e2 : 0.f;
                e3 = mrow1[j0 + 1] ? e3 : 0.f;
            }
            acc[nb][0] = e0; acc[nb][1] = e1; acc[nb][2] = e2; acc[nb][3] = e3;
            rs0 += e0 + e1; rs1 += e2 + e3;
        }

        // ---- O += P V  (P reused from accumulators as A fragments) ----
#pragma unroll
        for (int m = 0; m < 8; m++) {
            uint32_t aPh[4], aPl[4];
            split2(acc[2*m][0],     acc[2*m][1],     aPh[0], aPl[0]);
            split2(acc[2*m][2],     acc[2*m][3],     aPh[1], aPl[1]);
            split2(acc[2*m + 1][0], acc[2*m + 1][1], aPh[2], aPl[2]);
            split2(acc[2*m + 1][2], acc[2*m + 1][3], aPh[3], aPl[3]);
            uint32_t vbase = st + 32768 + (m >> 2) * 8192;
            int vgr = (m & 3) * 2 + ((lane >> 3) & 1);
#pragma unroll
            for (int nbp = 0; nbp < 4; nbp++) {
                int vrow = (nbp * 2 + (lane >> 4)) * 8 + (lane & 7);
                uint32_t vso = SWZ128((uint32_t)(vrow * 128 + vgr * 16));
                uint32_t vh4[4], vl4[4];
                ldsm_x4(vh4, vbase + vso);
                ldsm_x4(vl4, vbase + 16384 + vso);
                mma_bf16(Oacc[nbp*2],     aPh, vh4);
                mma_bf16(Oacc[nbp*2],     aPh, vl4);
                mma_bf16(Oacc[nbp*2],     aPl, vh4);
                mma_bf16(Oacc[nbp*2 + 1], aPh, vh4 + 2);
                mma_bf16(Oacc[nbp*2 + 1], aPh, vl4 + 2);
                mma_bf16(Oacc[nbp*2 + 1], aPl, vh4 + 2);
            }
        }
        __syncthreads();
    }

    // ---- finalize: O /= rowsum, split-bf16 write [B,T,D] ----
    rs0 += __shfl_xor_sync(0xffffffffu, rs0, 1);
    rs0 += __shfl_xor_sync(0xffffffffu, rs0, 2);
    rs1 += __shfl_xor_sync(0xffffffffu, rs1, 1);
    rs1 += __shfl_xor_sync(0xffffffffu, rs1, 2);
    float inv0 = 1.f / rs0, inv1 = 1.f / rs1;
    long long row0 = (long long)b * TT + qt * 128 + wid * 16 + (lane >> 2);
    long long row1 = row0 + 8;
#pragma unroll
    for (int nb = 0; nb < 8; nb++) {
        int c = h * DH + nb * 8 + (lane & 3) * 2;
        uint32_t hreg, lreg;
        split2(Oacc[nb][0] * inv0, Oacc[nb][1] * inv0, hreg, lreg);
        *(uint32_t*)(Oh_ + row0 * DD + c) = hreg;
        *(uint32_t*)(Ol_ + row0 * DD + c) = lreg;
        split2(Oacc[nb][2] * inv1, Oacc[nb][3] * inv1, hreg, lreg);
        *(uint32_t*)(Oh_ + row1 * DD + c) = hreg;
        *(uint32_t*)(Ol_ + row1 * DD + c) = lreg;
    }
}

// mask all-ones flag per (b, query-tile)
__global__ void mask_reduce(const int* __restrict__ mask, unsigned char* __restrict__ flags)
{
    int bid = blockIdx.x;
    int b = bid >> 4, qt = bid & 15;
    const int* base = mask + (long long)b * TT * TT + (long long)qt * 128 * TT;
    int ok = 1;
    for (int idx = threadIdx.x; idx < 128 * TT; idx += 256)
        ok &= (base[idx] != 0);
    ok = __all_sync(0xffffffffu, ok);
    __shared__ int red[8];
    if ((threadIdx.x & 31) == 0) red[threadIdx.x >> 5] = ok;
    __syncthreads();
    if (threadIdx.x == 0) {
        int r = 1;
#pragma unroll
        for (int w = 0; w < 8; w++) r &= red[w];
        flags[bid] = (unsigned char)r;
    }
}

// ================= SIMT helper kernels =================
__device__ __forceinline__ void split_write(bf16* Hh, bf16* Hl, long long idx, float v)
{
    bf16 h = __float2bfloat16(v);
    Hh[idx] = h;
    Hl[idx] = __float2bfloat16(v - __bfloat162float(h));
}

__global__ void effw_split(const float* __restrict__ W, const float* __restrict__ Am,
                           const float* __restrict__ Bm, bf16* __restrict__ Eh,
                           bf16* __restrict__ El, int IN, long long total)
{
    long long idx = (long long)blockIdx.x * 256 + threadIdx.x;
    if (idx >= total) return;
    float acc = W[idx];
    if (Am) {
        long long o = idx / IN;
        int i = (int)(idx % IN);
#pragma unroll
        for (int r = 0; r < RR; r++)
            acc += 0.125f * Bm[o * RR + r] * Am[(long long)r * IN + i];
    }
    split_write(Eh, El, idx, acc);
}

__global__ void rms_split(const float* __restrict__ X, const float* __restrict__ W,
                          bf16* __restrict__ Yh, bf16* __restrict__ Yl)
{
    int row = blockIdx.x;
    const float* x = X + (long long)row * DD;
    float v[4];
    float s = 0.f;
#pragma unroll
    for (int c = 0; c < 4; c++) {
        v[c] = x[threadIdx.x + c * 256];
        s += v[c] * v[c];
    }
    __shared__ float red[256];
    red[threadIdx.x] = s; __syncthreads();
    for (int o = 128; o > 0; o >>= 1) {
        if (threadIdx.x < o) red[threadIdx.x] += red[threadIdx.x + o];
        __syncthreads();
    }
    float rs = rsqrtf(red[0] * (1.0f / DD) + 1e-6f);
#pragma unroll
    for (int c = 0; c < 4; c++) {
        int i = threadIdx.x + c * 256;
        split_write(Yh, Yl, (long long)row * DD + i, W[i] * v[c] * rs);
    }
}

__global__ void posbias_kernel(const float* __restrict__ relb, float* __restrict__ bias)
{
    int idx = blockIdx.x * 256 + threadIdx.x;     // over T*T
    int i = idx >> 11;
    int j = idx & (TT - 1);
    const float* rb = relb + rel_bucket(j - i) * HH;
#pragma unroll
    for (int h = 0; h < HH; h++)
        bias[(long long)h * (TT * TT) + idx] = rb[h];
}

__global__ void geglu_split(const bf16* __restrict__ Hh, const bf16* __restrict__ Hl,
                            bf16* __restrict__ Gh, bf16* __restrict__ Gl)
{
    long long idx = (long long)blockIdx.x * 256 + threadIdx.x;  // over BT*2D
    long long row = idx >> 11;
    int col = (int)(idx & (2 * DD - 1));
    long long base = row * (4 * DD);
    float p1 = __bfloat162float(Hh[base + col]) + __bfloat162float(Hl[base + col]);
    float p2 = __bfloat162float(Hh[base + 2 * DD + col]) + __bfloat162float(Hl[base + 2 * DD + col]);
    float c3 = p2 * p2 * p2;
    float th = tanhf(0.7978845608028654f * (p2 + 0.044715f * c3));
    split_write(Gh, Gl, idx, p1 * 0.5f * p2 * (1.f + th));
}

// ================= launch =================
extern "C" void kernel_launch(void* const* d_in, const int* in_sizes, int n_in,
                              void* d_out, int out_size)
{
    const float* x       = (const float*)d_in[0];
    const int*   x_mask  = (const int*)  d_in[1];
    const float* norm1_w = (const float*)d_in[3];
    const float* norm3_w = (const float*)d_in[4];
    const float* wq_W = (const float*)d_in[5];
    const float* wq_A = (const float*)d_in[6];
    const float* wq_B = (const float*)d_in[7];
    const float* wk_W = (const float*)d_in[8];
    const float* wv_W = (const float*)d_in[9];
    const float* wv_A = (const float*)d_in[10];
    const float* wv_B = (const float*)d_in[11];
    const float* fc_W = (const float*)d_in[12];
    const float* fc_A = (const float*)d_in[13];
    const float* fc_B = (const float*)d_in[14];
    const float* relb = (const float*)d_in[15];
    const float* w1_W = (const float*)d_in[16];
    const float* w1_A = (const float*)d_in[17];
    const float* w1_B = (const float*)d_in[18];
    const float* w2_W = (const float*)d_in[19];
    const float* w2_A = (const float*)d_in[20];
    const float* w2_B = (const float*)d_in[21];

    float* outx    = (float*)d_out;                       // [B,T,D]
    float* outbias = (float*)d_out + (long long)BB*TT*DD; // [H,1,T,T]

    bf16 *qWh,*qWl,*kWh,*kWl,*vWh,*vWl,*fWh,*fWl,*w1h,*w1l,*w2h,*w2l;
    bf16 *Yh,*Yl,*Qh,*Ql,*Kh,*Kl,*Vth,*Vtl,*Oh,*Ol,*Hfh,*Hfl,*Gh,*Gl;
    float *X1;
    unsigned char *Fl;
    cudaGetSymbolAddress((void**)&qWh, g_qWh); cudaGetSymbolAddress((void**)&qWl, g_qWl);
    cudaGetSymbolAddress((void**)&kWh, g_kWh); cudaGetSymbolAddress((void**)&kWl, g_kWl);
    cudaGetSymbolAddress((void**)&vWh, g_vWh); cudaGetSymbolAddress((void**)&vWl, g_vWl);
    cudaGetSymbolAddress((void**)&fWh, g_fWh); cudaGetSymbolAddress((void**)&fWl, g_fWl);
    cudaGetSymbolAddress((void**)&w1h, g_w1h); cudaGetSymbolAddress((void**)&w1l, g_w1l);
    cudaGetSymbolAddress((void**)&w2h, g_w2h); cudaGetSymbolAddress((void**)&w2l, g_w2l);
    cudaGetSymbolAddress((void**)&Yh,  g_Yh);  cudaGetSymbolAddress((void**)&Yl,  g_Yl);
    cudaGetSymbolAddress((void**)&Qh,  g_Qh);  cudaGetSymbolAddress((void**)&Ql,  g_Ql);
    cudaGetSymbolAddress((void**)&Kh,  g_Kh);  cudaGetSymbolAddress((void**)&Kl,  g_Kl);
    cudaGetSymbolAddress((void**)&Vth, g_Vth); cudaGetSymbolAddress((void**)&Vtl, g_Vtl);
    cudaGetSymbolAddress((void**)&Oh,  g_Oh);  cudaGetSymbolAddress((void**)&Ol,  g_Ol);
    cudaGetSymbolAddress((void**)&Hfh, g_Hfh); cudaGetSymbolAddress((void**)&Hfl, g_Hfl);
    cudaGetSymbolAddress((void**)&Gh,  g_Gh);  cudaGetSymbolAddress((void**)&Gl,  g_Gl);
    cudaGetSymbolAddress((void**)&X1,  g_X1);
    cudaGetSymbolAddress((void**)&Fl,  g_flags);

    constexpr int GEMM_SMEM = 67584;  // max(2 stages = 65536, epilogue 128*132*4 = 67584)
    cudaFuncSetAttribute(tc_gemm<128,0>, cudaFuncAttributeMaxDynamicSharedMemorySize, GEMM_SMEM);
    cudaFuncSetAttribute(tc_gemm<128,1>, cudaFuncAttributeMaxDynamicSharedMemorySize, GEMM_SMEM);
    cudaFuncSetAttribute(tc_gemm<128,2>, cudaFuncAttributeMaxDynamicSharedMemorySize, GEMM_SMEM);
    cudaFuncSetAttribute(flash_attn,     cudaFuncAttributeMaxDynamicSharedMemorySize, FA_SMEM);

    // 1) split effective (LoRA-folded) weights
    effw_split<<<4096, 256>>>(wq_W, wq_A, wq_B, qWh, qWl, DD, (long long)DD*DD);
    effw_split<<<4096, 256>>>(wk_W, nullptr, nullptr, kWh, kWl, DD, (long long)DD*DD);
    effw_split<<<4096, 256>>>(wv_W, wv_A, wv_B, vWh, vWl, DD, (long long)DD*DD);
    effw_split<<<4096, 256>>>(fc_W, fc_A, fc_B, fWh, fWl, DD, (long long)DD*DD);
    effw_split<<<16384,256>>>(w1_W, w1_A, w1_B, w1h, w1l, DD, (long long)4*DD*DD);
    effw_split<<<8192, 256>>>(w2_W, w2_A, w2_B, w2h, w2l, 2*DD, (long long)2*DD*DD);

    // 2) positional bias output + mask flags
    posbias_kernel<<<(TT*TT)/256, 256>>>(relb, outbias);
    mask_reduce<<<BB*16, 256>>>(x_mask, Fl);

    // 3) RMSNorm 1 -> split Y
    rms_split<<<BT, 256>>>(x, norm1_w, Yh, Yl);

    // 4) Q, K projections; V projection transposed [B][D][T]
    tc_gemm<128,1><<<dim3(8,32,1), 256, GEMM_SMEM>>>(
        Yh, Yl, qWh, qWl, nullptr, nullptr, Qh, Ql,
        DD, DD, DD, DD, 1, 0,0, 0,0, 0,0);
    tc_gemm<128,1><<<dim3(8,32,1), 256, GEMM_SMEM>>>(
        Yh, Yl, kWh, kWl, nullptr, nullptr, Kh, Kl,
        DD, DD, DD, DD, 1, 0,0, 0,0, 0,0);
    tc_gemm<128,2><<<dim3(8,16,2), 256, GEMM_SMEM>>>(
        Yh, Yl, vWh, vWl, nullptr, nullptr, Vth, Vtl,
        DD, DD, DD, TT, 1,
        (long long)TT*DD, 0, 0, 0, (long long)DD*TT, 0);

    // 5) fused attention -> split O [B,T,D]
    flash_attn<<<dim3(16, BB*HH), 256, FA_SMEM>>>(
        Qh, Ql, Kh, Kl, Vth, Vtl, relb, x_mask, Fl, Oh, Ol);

    // 6) X1 = x + O @ Fc^T  (fp32)
    tc_gemm<128,0><<<dim3(8,32,1), 256, GEMM_SMEM>>>(
        Oh, Ol, fWh, fWl, X1, x, nullptr, nullptr,
        DD, DD, DD, DD, 1, 0,0, 0,0, 0,0);

    // 7) RMSNorm 3 -> split Y
    rms_split<<<BT, 256>>>(X1, norm3_w, Yh, Yl);

    // 8) H = Y @ W1^T  (split out)
    tc_gemm<128,1><<<dim3(32,32,1), 256, GEMM_SMEM>>>(
        Yh, Yl, w1h, w1l, nullptr, nullptr, Hfh, Hfl,
        DD, DD, DD, 4*DD, 1, 0,0, 0,0, 0,0);

    // 9) GEGLU (split in/out)
    geglu_split<<<(BT*2*DD)/256, 256>>>(Hfh, Hfl, Gh, Gl);

    // 10) out_x = X1 + G @ W2^T (fp32)
    tc_gemm<128,0><<<dim3(8,32,1), 256, GEMM_SMEM>>>(
        Gh, Gl, w2h, w2l, outx, X1, nullptr, nullptr,
        2*DD, 2*DD, 2*DD, DD, 1, 0,0, 0,0, 0,0);
}

// round 17
// speedup vs baseline: 1.0292x; 1.0292x over previous
#include <cuda_runtime.h>
#include <cuda_bf16.h>
#include <math.h>
#include <stdint.h>

// ---------------- problem constants ----------------
#define BB 2
#define TT 2048
#define DD 1024
#define HH 16
#define DH 64
#define RR 8
#define BT (BB*TT)            // 4096 tokens
typedef __nv_bfloat16 bf16;

// ================= low-level helpers (baseline PTX ISA only) =================
__device__ __forceinline__ uint32_t smem_u32(const void* p) {
    uint32_t a;
    asm("{ .reg .u64 t; cvta.to.shared.u64 t, %1; cvt.u32.u64 %0, t; }" : "=r"(a) : "l"(p));
    return a;
}
__device__ __forceinline__ void ldsm_x4(uint32_t* r, uint32_t addr) {
    asm volatile("ldmatrix.sync.aligned.m8n8.x4.shared.b16 {%0,%1,%2,%3}, [%4];"
        : "=r"(r[0]), "=r"(r[1]), "=r"(r[2]), "=r"(r[3]) : "r"(addr));
}
__device__ __forceinline__ void mma_bf16(float* d, const uint32_t* a, const uint32_t* b) {
    asm volatile(
        "mma.sync.aligned.m16n8k16.row.col.f32.bf16.bf16.f32 "
        "{%0,%1,%2,%3}, {%4,%5,%6,%7}, {%8,%9}, {%0,%1,%2,%3};"
        : "+f"(d[0]), "+f"(d[1]), "+f"(d[2]), "+f"(d[3])
        : "r"(a[0]), "r"(a[1]), "r"(a[2]), "r"(a[3]), "r"(b[0]), "r"(b[1]));
}
__device__ __forceinline__ void cp16(uint32_t dst, const void* src) {
    asm volatile("cp.async.cg.shared.global [%0], [%1], 16;" :: "r"(dst), "l"(src));
}
#define CP_COMMIT() asm volatile("cp.async.commit_group;" ::: "memory")
#define CP_WAIT1()  asm volatile("cp.async.wait_group 1;" ::: "memory")
#define CP_WAIT0()  asm volatile("cp.async.wait_group 0;" ::: "memory")
#define SWZ128(off) ((off) ^ (((off) >> 3) & 0x70))

__device__ __forceinline__ void split2(float x, float y, uint32_t& h, uint32_t& l) {
    bf16 hx = __float2bfloat16(x), hy = __float2bfloat16(y);
    bf16 lx = __float2bfloat16(x - __bfloat162float(hx));
    bf16 ly = __float2bfloat16(y - __bfloat162float(hy));
    __nv_bfloat162 hp = __halves2bfloat162(hx, hy);
    __nv_bfloat162 lp = __halves2bfloat162(lx, ly);
    h = *(uint32_t*)&hp; l = *(uint32_t*)&lp;
}

// ---------------- scratch (__device__ globals; alloc-free) ----------------
__device__ __align__(256) bf16 g_qWh[DD*DD],  g_qWl[DD*DD];
__device__ __align__(256) bf16 g_kWh[DD*DD],  g_kWl[DD*DD];
__device__ __align__(256) bf16 g_vWh[DD*DD],  g_vWl[DD*DD];
__device__ __align__(256) bf16 g_fWh[DD*DD],  g_fWl[DD*DD];
__device__ __align__(256) bf16 g_w1h[4*DD*DD], g_w1l[4*DD*DD];
__device__ __align__(256) bf16 g_w2h[2*DD*DD], g_w2l[2*DD*DD];
__device__ __align__(256) bf16 g_Yh[BT*DD],  g_Yl[BT*DD];
__device__ __align__(256) bf16 g_Qh[BT*DD],  g_Ql[BT*DD];
__device__ __align__(256) bf16 g_Kh[BT*DD],  g_Kl[BT*DD];
__device__ __align__(256) bf16 g_Vth[BT*DD], g_Vtl[BT*DD];   // [B][D][T]
__device__ __align__(256) bf16 g_Oh[BT*DD],  g_Ol[BT*DD];
__device__ __align__(256) bf16 g_Gh[BT*2*DD],  g_Gl[BT*2*DD];
__device__ __align__(256) float g_X1[BT*DD];
__device__ unsigned char g_flags[BB*16];

// ================= HMMA split-bf16 GEMM (R9 config: BK=64, 2 stages, occ 1) ==========
// C[m,n] = sum_k A[m,k]*B[n,k], hi/lo split bf16 operands, fp32 accumulation.
// 256 threads; BM=128; warp grid 4x2 -> warp tile 32 x (BN/2).
// EPI: 0 = fp32 out (+Res), 1 = split bf16 out, 2 = split bf16 TRANSPOSED out,
//      3 = fused GEGLU: B rows 0-63 <- W1[bn/2 + r], rows 64-127 <- W1[2048 + bn/2 + r];
//          epilogue writes split G[:, bn/2 .. bn/2+64) = p1 * gelu_tanh(p2).
template<int BN, int EPI>
__global__ void __launch_bounds__(256, 1)
tc_gemm(const bf16* __restrict__ Ah, const bf16* __restrict__ Al,
        const bf16* __restrict__ Bh, const bf16* __restrict__ Bl,
        float* __restrict__ C, const float* __restrict__ Res,
        bf16* __restrict__ Ch, bf16* __restrict__ Cl,
        int K, int lda, int ldb, int ldc, int zdiv,
        long long sA1, long long sA2, long long sB1, long long sB2,
        long long sC1, long long sC2)
{
    constexpr int WTN  = BN / 2;
    constexpr int NB8  = WTN / 8;
    constexpr int A_HI = 0;
    constexpr int A_LO = 16384;
    constexpr int B_HI = 32768;
    constexpr int B_LO = 32768 + BN * 128;
    constexpr int STAGE = 32768 + BN * 256;

    extern __shared__ __align__(128) char smem[];
    uint32_t sb = smem_u32(smem);
    int tid = threadIdx.x, wid = tid >> 5, lane = tid & 31;
    int wm = wid & 3, wn = wid >> 2;

    int z = blockIdx.z, z1 = z / zdiv, z2 = z - z1 * zdiv;
    long long aoff = z1 * sA1 + z2 * sA2;
    long long boff = z1 * sB1 + z2 * sB2;
    long long coff = z1 * sC1 + z2 * sC2;
    Ah += aoff; Al += aoff; Bh += boff; Bl += boff;
    if (EPI == 0) { C += coff; if (Res) Res += coff; }
    else          { Ch += coff; Cl += coff; }
    int bm = blockIdx.y * 128;
    int bn = blockIdx.x * BN;

    float acc[2][NB8][4];
#pragma unroll
    for (int mt = 0; mt < 2; mt++)
#pragma unroll
        for (int nb = 0; nb < NB8; nb++)
#pragma unroll
            for (int i = 0; i < 4; i++) acc[mt][nb][i] = 0.f;

    const int NC = K >> 6;

    auto issue_chunk = [&](int c, int s) {
        int k0 = c << 6;
        uint32_t st = sb + s * STAGE;
#pragma unroll
        for (int it = 0; it < 4; it++) {
            int idx = it * 256 + tid;
            int row = idx >> 3, g16 = idx & 7;
            long long g = (long long)(bm + row) * lda + k0 + g16 * 8;
            uint32_t so = SWZ128((uint32_t)(row * 128 + g16 * 16));
            cp16(st + A_HI + so, Ah + g);
            cp16(st + A_LO + so, Al + g);
        }
#pragma unroll
        for (int it = 0; it < BN / 32; it++) {
            int idx = it * 256 + tid;
            int row = idx >> 3, g16 = idx & 7;
            long long grow;
            if (EPI == 3)
                grow = (row < 64) ? (long long)((bn >> 1) + row)
                                  : (long long)(2048 + (bn >> 1) + row - 64);
            else
                grow = (long long)(bn + row);
            long long g = grow * ldb + k0 + g16 * 8;
            uint32_t so = SWZ128((uint32_t)(row * 128 + g16 * 16));
            cp16(st + B_HI + so, Bh + g);
            cp16(st + B_LO + so, Bl + g);
        }
        CP_COMMIT();
    };

    issue_chunk(0, 0);

    for (int c = 0; c < NC; c++) {
        if (c + 1 < NC) { issue_chunk(c + 1, (c + 1) & 1); CP_WAIT1(); }
        else            { CP_WAIT0(); }
        __syncthreads();

        uint32_t st = sb + (c & 1) * STAGE;
#pragma unroll
        for (int j = 0; j < 4; j++) {
            uint32_t aH[2][4], aL[2][4];
#pragma unroll
            for (int mt = 0; mt < 2; mt++) {
                int row = wm * 32 + mt * 16 + (lane & 15);
                int gr  = j * 2 + (lane >> 4);
                uint32_t so = SWZ128((uint32_t)(row * 128 + gr * 16));
                ldsm_x4(aH[mt], st + A_HI + so);
                ldsm_x4(aL[mt], st + A_LO + so);
            }
            uint32_t bH[NB8][2], bL[NB8][2];
#pragma unroll
            for (int nbp = 0; nbp < NB8 / 2; nbp++) {
                int row = wn * WTN + (nbp * 2 + (lane >> 4)) * 8 + (lane & 7);
                int gr  = j * 2 + ((lane >> 3) & 1);
                uint32_t so = SWZ128((uint32_t)(row * 128 + gr * 16));
                uint32_t r4[4];
                ldsm_x4(r4, st + B_HI + so);
                bH[nbp*2][0] = r4[0]; bH[nbp*2][1] = r4[1];
                bH[nbp*2+1][0] = r4[2]; bH[nbp*2+1][1] = r4[3];
                ldsm_x4(r4, st + B_LO + so);
                bL[nbp*2][0] = r4[0]; bL[nbp*2][1] = r4[1];
                bL[nbp*2+1][0] = r4[2]; bL[nbp*2+1][1] = r4[3];
            }
#pragma unroll
            for (int mt = 0; mt < 2; mt++)
#pragma unroll
                for (int nb = 0; nb < NB8; nb++) {
                    mma_bf16(acc[mt][nb], aH[mt], bH[nb]);
                    mma_bf16(acc[mt][nb], aH[mt], bL[nb]);
                    mma_bf16(acc[mt][nb], aL[mt], bH[nb]);
                }
        }
        __syncthreads();
    }

    // ---- epilogue: bounce accumulators through (reused) stage smem ----
    constexpr int BNP = BN + 4;
    float* sE = (float*)smem;
#pragma unroll
    for (int mt = 0; mt < 2; mt++)
#pragma unroll
        for (int nb = 0; nb < NB8; nb++) {
            int r0 = wm * 32 + mt * 16 + (lane >> 2);
            int c0 = wn * WTN + nb * 8 + (lane & 3) * 2;
            sE[r0 * BNP + c0]       = acc[mt][nb][0];
            sE[r0 * BNP + c0 + 1]   = acc[mt][nb][1];
            sE[(r0+8) * BNP + c0]   = acc[mt][nb][2];
            sE[(r0+8) * BNP + c0+1] = acc[mt][nb][3];
        }
    __syncthreads();

    if (EPI == 2) {
        int f = tid >> 1, seg = tid & 1;
        long long ob = (long long)(bn + f) * ldc + bm + seg * 64;
#pragma unroll
        for (int cc = 0; cc < 64; cc += 4) {
            bf16 h[4], l[4];
#pragma unroll
            for (int i = 0; i < 4; i++) {
                float v = sE[(seg * 64 + cc + i) * BNP + f];
                h[i] = __float2bfloat16(v);
                l[i] = __float2bfloat16(v - __bfloat162float(h[i]));
            }
            *(__nv_bfloat162*)(Ch + ob + cc)     = __halves2bfloat162(h[0], h[1]);
            *(__nv_bfloat162*)(Ch + ob + cc + 2) = __halves2bfloat162(h[2], h[3]);
            *(__nv_bfloat162*)(Cl + ob + cc)     = __halves2bfloat162(l[0], l[1]);
            *(__nv_bfloat162*)(Cl + ob + cc + 2) = __halves2bfloat162(l[2], l[3]);
        }
    } else if (EPI == 3) {
        // cols 0-63 = p1, cols 64-127 = p2; write split G[:, bn/2 .. bn/2+64)
#pragma unroll
        for (int p = 0; p < 8; p++) {
            int idx = p * 256 + tid;
            int r  = idx >> 4;
            int cq = (idx & 15) * 4;
            float gg[4];
#pragma unroll
            for (int i = 0; i < 4; i++) {
                float p1 = sE[r * BNP + cq + i];
                float p2 = sE[r * BNP + 64 + cq + i];
                float u  = 0.7978845608028654f * (p2 + 0.044715f * p2 * p2 * p2);
                float th = 1.f - 2.f / (1.f + __expf(2.f * u));
                gg[i] = p1 * 0.5f * p2 * (1.f + th);
            }
            long long ob = (long long)(bm + r) * ldc + (bn >> 1) + cq;
            uint32_t h0, l0, h1, l1;
            split2(gg[0], gg[1], h0, l0);
            split2(gg[2], gg[3], h1, l1);
            *(uint32_t*)(Ch + ob)     = h0;
            *(uint32_t*)(Ch + ob + 2) = h1;
            *(uint32_t*)(Cl + ob)     = l0;
            *(uint32_t*)(Cl + ob + 2) = l1;
        }
    } else {
        constexpr int NQ = BN / 4;
#pragma unroll
        for (int p = 0; p < BN / 8; p++) {
            int idx = p * 256 + tid;
            int r  = idx / NQ;
            int cq = (idx % NQ) * 4;
            float v0 = sE[r * BNP + cq + 0];
            float v1 = sE[r * BNP + cq + 1];
            float v2 = sE[r * BNP + cq + 2];
            float v3 = sE[r * BNP + cq + 3];
            long long ob = (long long)(bm + r) * ldc + bn + cq;
            if (EPI == 0) {
                if (Res) {
                    float4 rr = *(const float4*)(Res + ob);
                    v0 += rr.x; v1 += rr.y; v2 += rr.z; v3 += rr.w;
                }
                float4 o; o.x = v0; o.y = v1; o.z = v2; o.w = v3;
                *(float4*)(C + ob) = o;
            } else {
                uint32_t h0, l0, h1, l1;
                split2(v0, v1, h0, l0);
                split2(v2, v3, h1, l1);
                *(uint32_t*)(Ch + ob)     = h0;
                *(uint32_t*)(Ch + ob + 2) = h1;
                *(uint32_t*)(Cl + ob)     = l0;
                *(uint32_t*)(Cl + ob + 2) = l1;
            }
        }
    }
}

// ================= T5 bucket =================
__device__ __forceinline__ int rel_bucket(int rel)
{
    int base = (rel > 0) ? 16 : 0;
    int r = rel < 0 ? -rel : rel;
    int v;
    if      (r <  8) v = r;
    else if (r < 12) v = 8;
    else if (r < 16) v = 9;
    else if (r < 23) v = 10;
    else if (r < 32) v = 11;
    else if (r < 46) v = 12;
    else if (r < 64) v = 13;
    else if (r < 91) v = 14;
    else             v = 15;
    return base + v;
}

// ================= flash attention (fused QK^T + softmax + PV) =================
#define FA_STG   32768
#define FA_STAGE 65536
#define FA_LUT   163840
#define FA_SMEM  164992

__global__ void __launch_bounds__(256, 1)
flash_attn(const bf16* __restrict__ Qh_, const bf16* __restrict__ Ql_,
           const bf16* __restrict__ Kh_, const bf16* __restrict__ Kl_,
           const bf16* __restrict__ Vh_, const bf16* __restrict__ Vl_,
           const float* __restrict__ relb, const int* __restrict__ mask,
           const unsigned char* __restrict__ flags,
           bf16* __restrict__ Oh_, bf16* __restrict__ Ol_)
{
    extern __shared__ __align__(128) char smem[];
    uint32_t sb = smem_u32(smem);
    int tid = threadIdx.x, wid = tid >> 5, lane = tid & 31;
    int qt = blockIdx.x, bh = blockIdx.y;
    int b = bh >> 4, h = bh & (HH - 1);

    float* lutF = (float*)(smem + FA_LUT);
    for (int ii = tid; ii < 257; ii += 256)
        lutF[ii] = __expf(relb[rel_bucket(ii - 128) * HH + h]);
    bool allone = flags[b * 16 + qt] != 0;

    const bf16* Qbh = Qh_ + ((long long)b * TT + qt * 128) * DD + h * DH;
    const bf16* Qbl = Ql_ + ((long long)b * TT + qt * 128) * DD + h * DH;
    const bf16* Kbh = Kh_ + (long long)b * TT * DD + h * DH;
    const bf16* Kbl = Kl_ + (long long)b * TT * DD + h * DH;
    const bf16* Vbh = Vh_ + (long long)b * DD * TT + (long long)h * DH * TT;
    const bf16* Vbl = Vl_ + (long long)b * DD * TT + (long long)h * DH * TT;

#pragma unroll
    for (int it = 0; it < 4; it++) {
        int idx = it * 256 + tid;
        int row = idx >> 3, g16 = idx & 7;
        long long g = (long long)row * DD + g16 * 8;
        uint32_t so = SWZ128((uint32_t)(row * 128 + g16 * 16));
        cp16(sb + so,         Qbh + g);
        cp16(sb + 16384 + so, Qbl + g);
    }
    CP_COMMIT();

    auto issue_kv = [&](int t, int s) {
        uint32_t st = sb + FA_STG + s * FA_STAGE;
#pragma unroll
        for (int it = 0; it < 4; it++) {
            int idx = it * 256 + tid;
            int row = idx >> 3, g16 = idx & 7;
            long long g = (long long)(t * 128 + row) * DD + g16 * 8;
            uint32_t so = SWZ128((uint32_t)(row * 128 + g16 * 16));
            cp16(st + so,         Kbh + g);
            cp16(st + 16384 + so, Kbl + g);
        }
#pragma unroll
        for (int it = 0; it < 4; it++) {
            int idx = it * 256 + tid;
            int chunk = idx >> 9, row = (idx >> 3) & 63, g16 = idx & 7;
            long long g = (long long)row * TT + t * 128 + chunk * 64 + g16 * 8;
            uint32_t so = (uint32_t)(chunk * 8192) + SWZ128((uint32_t)(row * 128 + g16 * 16));
            cp16(st + 32768 + so, Vbh + g);
            cp16(st + 49152 + so, Vbl + g);
        }
        CP_COMMIT();
    };
    issue_kv(0, 0);

    float Oacc[8][4];
#pragma unroll
    for (int nb = 0; nb < 8; nb++)
#pragma unroll
        for (int q = 0; q < 4; q++) Oacc[nb][q] = 0.f;
    float rs0 = 0.f, rs1 = 0.f;

    int i0 = qt * 128 + wid * 16 + (lane >> 2);
    const int* mrow0 = mask + (long long)b * TT * TT + (long long)i0 * TT;
    const int* mrow1 = mrow0 + 8 * TT;

    for (int t = 0; t < TT / 128; t++) {
        if (t + 1 < TT / 128) { issue_kv(t + 1, (t + 1) & 1); CP_WAIT1(); }
        else                  { CP_WAIT0(); }
        __syncthreads();
        uint32_t st = sb + FA_STG + (t & 1) * FA_STAGE;

        float acc[16][4];
#pragma unroll
        for (int nb = 0; nb < 16; nb++)
#pragma unroll
            for (int q = 0; q < 4; q++) acc[nb][q] = 0.f;

#pragma unroll
        for (int j = 0; j < 4; j++) {
            uint32_t aH[4], aL[4];
            {
                int row = wid * 16 + (lane & 15);
                int gr  = j * 2 + (lane >> 4);
                uint32_t so = SWZ128((uint32_t)(row * 128 + gr * 16));
                ldsm_x4(aH, sb + so);
                ldsm_x4(aL, sb + 16384 + so);
            }
#pragma unroll
            for (int nbp = 0; nbp < 8; nbp++) {
                int brow = (nbp * 2 + (lane >> 4)) * 8 + (lane & 7);
                int bgr  = j * 2 + ((lane >> 3) & 1);
                uint32_t bso = SWZ128((uint32_t)(brow * 128 + bgr * 16));
                uint32_t bh4[4], bl4[4];
                ldsm_x4(bh4, st + bso);
                ldsm_x4(bl4, st + 16384 + bso);
                mma_bf16(acc[nbp*2],     aH, bh4);
                mma_bf16(acc[nbp*2],     aH, bl4);
                mma_bf16(acc[nbp*2],     aL, bh4);
                mma_bf16(acc[nbp*2 + 1], aH, bh4 + 2);
                mma_bf16(acc[nbp*2 + 1], aH, bl4 + 2);
                mma_bf16(acc[nbp*2 + 1], aL, bh4 + 2);
            }
        }

        int jb = t * 128 + (lane & 3) * 2;
#pragma unroll
        for (int nb = 0; nb < 16; nb++) {
            int j0  = jb + nb * 8;
            int d0  = j0 - i0;
            int d1  = d0 - 8;
            float e0 = __expf(acc[nb][0] * 0.125f) * lutF[min(max(d0,     -128), 128) + 128];
            float e1 = __expf(acc[nb][1] * 0.125f) * lutF[min(max(d0 + 1, -128), 128) + 128];
            float e2 = __expf(acc[nb][2] * 0.125f) * lutF[min(max(d1,     -128), 128) + 128];
            float e3 = __expf(acc[nb][3] * 0.125f) * lutF[min(max(d1 + 1, -128), 128) + 128];
            if (!allone) {
                e0 = mrow0[j0]     ? e0 : 0.f;
                e1 = mrow0[j0 + 1] ? e1 : 0.f;
                e2 = mrow1[j0]     ? e2 : 0.f;
                e3 = mrow1[j0 + 1] ? e3 : 0.f;
            }
            acc[nb][0] = e0; acc[nb][1] = e1; acc[nb][2] = e2; acc[nb][3] = e3;
            rs0 += e0 + e1; rs1 += e2 + e3;
        }

#pragma unroll
        for (int m = 0; m < 8; m++) {
            uint32_t aPh[4], aPl[4];
            split2(acc[2*m][0],     acc[2*m][1],     aPh[0], aPl[0]);
            split2(acc[2*m][2],     acc[2*m][3],     aPh[1], aPl[1]);
            split2(acc[2*m + 1][0], acc[2*m + 1][1], aPh[2], aPl[2]);
            split2(acc[2*m + 1][2], acc[2*m + 1][3], aPh[3], aPl[3]);
            uint32_t vbase = st + 32768 + (m >> 2) * 8192;
            int vgr = (m & 3) * 2 + ((lane >> 3) & 1);
#pragma unroll
            for (int nbp = 0; nbp < 4; nbp++) {
                int vrow = (nbp * 2 + (lane >> 4)) * 8 + (lane & 7);
                uint32_t vso = SWZ128((uint32_t)(vrow * 128 + vgr * 16));
                uint32_t vh4[4], vl4[4];
                ldsm_x4(vh4, vbase + vso);
                ldsm_x4(vl4, vbase + 16384 + vso);
                mma_bf16(Oacc[nbp*2],     aPh, vh4);
                mma_bf16(Oacc[nbp*2],     aPh, vl4);
                mma_bf16(Oacc[nbp*2],     aPl, vh4);
                mma_bf16(Oacc[nbp*2 + 1], aPh, vh4 + 2);
                mma_bf16(Oacc[nbp*2 + 1], aPh, vl4 + 2);
                mma_bf16(Oacc[nbp*2 + 1], aPl, vh4 + 2);
            }
        }
        __syncthreads();
    }

    rs0 += __shfl_xor_sync(0xffffffffu, rs0, 1);
    rs0 += __shfl_xor_sync(0xffffffffu, rs0, 2);
    rs1 += __shfl_xor_sync(0xffffffffu, rs1, 1);
    rs1 += __shfl_xor_sync(0xffffffffu, rs1, 2);
    float inv0 = 1.f / rs0, inv1 = 1.f / rs1;
    long long row0 = (long long)b * TT + qt * 128 + wid * 16 + (lane >> 2);
    long long row1 = row0 + 8;
#pragma unroll
    for (int nb = 0; nb < 8; nb++) {
        int c = h * DH + nb * 8 + (lane & 3) * 2;
        uint32_t hreg, lreg;
        split2(Oacc[nb][0] * inv0, Oacc[nb][1] * inv0, hreg, lreg);
        *(uint32_t*)(Oh_ + row0 * DD + c) = hreg;
        *(uint32_t*)(Ol_ + row0 * DD + c) = lreg;
        split2(Oacc[nb][2] * inv1, Oacc[nb][3] * inv1, hreg, lreg);
        *(uint32_t*)(Oh_ + row1 * DD + c) = hreg;
        *(uint32_t*)(Ol_ + row1 * DD + c) = lreg;
    }
}

// mask all-ones flag per (b, query-tile)
__global__ void mask_reduce(const int* __restrict__ mask, unsigned char* __restrict__ flags)
{
    int bid = blockIdx.x;
    int b = bid >> 4, qt = bid & 15;
    const int* base = mask + (long long)b * TT * TT + (long long)qt * 128 * TT;
    int ok = 1;
    for (int idx = threadIdx.x; idx < 128 * TT; idx += 256)
        ok &= (base[idx] != 0);
    ok = __all_sync(0xffffffffu, ok);
    __shared__ int red[8];
    if ((threadIdx.x & 31) == 0) red[threadIdx.x >> 5] = ok;
    __syncthreads();
    if (threadIdx.x == 0) {
        int r = 1;
#pragma unroll
        for (int w = 0; w < 8; w++) r &= red[w];
        flags[bid] = (unsigned char)r;
    }
}

// ================= SIMT helper kernels =================
__device__ __forceinline__ void split_write(bf16* Hh, bf16* Hl, long long idx, float v)
{
    bf16 h = __float2bfloat16(v);
    Hh[idx] = h;
    Hl[idx] = __float2bfloat16(v - __bfloat162float(h));
}

__global__ void effw_split(const float* __restrict__ W, const float* __restrict__ Am,
                           const float* __restrict__ Bm, bf16* __restrict__ Eh,
                           bf16* __restrict__ El, int IN, long long total)
{
    long long idx = (long long)blockIdx.x * 256 + threadIdx.x;
    if (idx >= total) return;
    float acc = W[idx];
    if (Am) {
        long long o = idx / IN;
        int i = (int)(idx % IN);
#pragma unroll
        for (int r = 0; r < RR; r++)
            acc += 0.125f * Bm[o * RR + r] * Am[(long long)r * IN + i];
    }
    split_write(Eh, El, idx, acc);
}

__global__ void rms_split(const float* __restrict__ X, const float* __restrict__ W,
                          bf16* __restrict__ Yh, bf16* __restrict__ Yl)
{
    int row = blockIdx.x;
    const float* x = X + (long long)row * DD;
    float v[4];
    float s = 0.f;
#pragma unroll
    for (int c = 0; c < 4; c++) {
        v[c] = x[threadIdx.x + c * 256];
        s += v[c] * v[c];
    }
    __shared__ float red[256];
    red[threadIdx.x] = s; __syncthreads();
    for (int o = 128; o > 0; o >>= 1) {
        if (threadIdx.x < o) red[threadIdx.x] += red[threadIdx.x + o];
        __syncthreads();
    }
    float rs = rsqrtf(red[0] * (1.0f / DD) + 1e-6f);
#pragma unroll
    for (int c = 0; c < 4; c++) {
        int i = threadIdx.x + c * 256;
        split_write(Yh, Yl, (long long)row * DD + i, W[i] * v[c] * rs);
    }
}

__global__ void posbias_kernel(const float* __restrict__ relb, float* __restrict__ bias)
{
    int idx = blockIdx.x * 256 + threadIdx.x;     // over T*T
    int i = idx >> 11;
    int j = idx & (TT - 1);
    const float* rb = relb + rel_bucket(j - i) * HH;
#pragma unroll
    for (int h = 0; h < HH; h++)
        bias[(long long)h * (TT * TT) + idx] = rb[h];
}

// ================= launch =================
extern "C" void kernel_launch(void* const* d_in, const int* in_sizes, int n_in,
                              void* d_out, int out_size)
{
    const float* x       = (const float*)d_in[0];
    const int*   x_mask  = (const int*)  d_in[1];
    const float* norm1_w = (const float*)d_in[3];
    const float* norm3_w = (const float*)d_in[4];
    const float* wq_W = (const float*)d_in[5];
    const float* wq_A = (const float*)d_in[6];
    const float* wq_B = (const float*)d_in[7];
    const float* wk_W = (const float*)d_in[8];
    const float* wv_W = (const float*)d_in[9];
    const float* wv_A = (const float*)d_in[10];
    const float* wv_B = (const float*)d_in[11];
    const float* fc_W = (const float*)d_in[12];
    const float* fc_A = (const float*)d_in[13];
    const float* fc_B = (const float*)d_in[14];
    const float* relb = (const float*)d_in[15];
    const float* w1_W = (const float*)d_in[16];
    const float* w1_A = (const float*)d_in[17];
    const float* w1_B = (const float*)d_in[18];
    const float* w2_W = (const float*)d_in[19];
    const float* w2_A = (const float*)d_in[20];
    const float* w2_B = (const float*)d_in[21];

    float* outx    = (float*)d_out;                       // [B,T,D]
    float* outbias = (float*)d_out + (long long)BB*TT*DD; // [H,1,T,T]

    bf16 *qWh,*qWl,*kWh,*kWl,*vWh,*vWl,*fWh,*fWl,*w1h,*w1l,*w2h,*w2l;
    bf16 *Yh,*Yl,*Qh,*Ql,*Kh,*Kl,*Vth,*Vtl,*Oh,*Ol,*Gh,*Gl;
    float *X1;
    unsigned char *Fl;
    cudaGetSymbolAddress((void**)&qWh, g_qWh); cudaGetSymbolAddress((void**)&qWl, g_qWl);
    cudaGetSymbolAddress((void**)&kWh, g_kWh); cudaGetSymbolAddress((void**)&kWl, g_kWl);
    cudaGetSymbolAddress((void**)&vWh, g_vWh); cudaGetSymbolAddress((void**)&vWl, g_vWl);
    cudaGetSymbolAddress((void**)&fWh, g_fWh); cudaGetSymbolAddress((void**)&fWl, g_fWl);
    cudaGetSymbolAddress((void**)&w1h, g_w1h); cudaGetSymbolAddress((void**)&w1l, g_w1l);
    cudaGetSymbolAddress((void**)&w2h, g_w2h); cudaGetSymbolAddress((void**)&w2l, g_w2l);
    cudaGetSymbolAddress((void**)&Yh,  g_Yh);  cudaGetSymbolAddress((void**)&Yl,  g_Yl);
    cudaGetSymbolAddress((void**)&Qh,  g_Qh);  cudaGetSymbolAddress((void**)&Ql,  g_Ql);
    cudaGetSymbolAddress((void**)&Kh,  g_Kh);  cudaGetSymbolAddress((void**)&Kl,  g_Kl);
    cudaGetSymbolAddress((void**)&Vth, g_Vth); cudaGetSymbolAddress((void**)&Vtl, g_Vtl);
    cudaGetSymbolAddress((void**)&Oh,  g_Oh);  cudaGetSymbolAddress((void**)&Ol,  g_Ol);
    cudaGetSymbolAddress((void**)&Gh,  g_Gh);  cudaGetSymbolAddress((void**)&Gl,  g_Gl);
    cudaGetSymbolAddress((void**)&X1,  g_X1);
    cudaGetSymbolAddress((void**)&Fl,  g_flags);

    constexpr int SMEM128 = 2 * (32768 + 128 * 256);  // 131072
    cudaFuncSetAttribute(tc_gemm<128,0>, cudaFuncAttributeMaxDynamicSharedMemorySize, SMEM128);
    cudaFuncSetAttribute(tc_gemm<128,1>, cudaFuncAttributeMaxDynamicSharedMemorySize, SMEM128);
    cudaFuncSetAttribute(tc_gemm<128,2>, cudaFuncAttributeMaxDynamicSharedMemorySize, SMEM128);
    cudaFuncSetAttribute(tc_gemm<128,3>, cudaFuncAttributeMaxDynamicSharedMemorySize, SMEM128);
    cudaFuncSetAttribute(flash_attn,     cudaFuncAttributeMaxDynamicSharedMemorySize, FA_SMEM);

    // --- launches ordered so ncu (-s 5 -c 1) profiles the K-projection GEMM ---

    // 0-2) QKV effective weights
    effw_split<<<4096, 256>>>(wq_W, wq_A, wq_B, qWh, qWl, DD, (long long)DD*DD);
    effw_split<<<4096, 256>>>(wk_W, nullptr, nullptr, kWh, kWl, DD, (long long)DD*DD);
    effw_split<<<4096, 256>>>(wv_W, wv_A, wv_B, vWh, vWl, DD, (long long)DD*DD);

    // 3) RMSNorm 1 -> split Y
    rms_split<<<BT, 256>>>(x, norm1_w, Yh, Yl);

    // 4-6) Q, K projections; V projection transposed [B][D][T]
    tc_gemm<128,1><<<dim3(8,32,1), 256, SMEM128>>>(
        Yh, Yl, qWh, qWl, nullptr, nullptr, Qh, Ql,
        DD, DD, DD, DD, 1, 0,0, 0,0, 0,0);
    tc_gemm<128,1><<<dim3(8,32,1), 256, SMEM128>>>(       // <- profiled launch
        Yh, Yl, kWh, kWl, nullptr, nullptr, Kh, Kl,
        DD, DD, DD, DD, 1, 0,0, 0,0, 0,0);
    tc_gemm<128,2><<<dim3(8,16,2), 256, SMEM128>>>(
        Yh, Yl, vWh, vWl, nullptr, nullptr, Vth, Vtl,
        DD, DD, DD, TT, 1,
        (long long)TT*DD, 0, 0, 0, (long long)DD*TT, 0);

    // 7-8) mask flags + fused attention -> split O [B,T,D]
    mask_reduce<<<BB*16, 256>>>(x_mask, Fl);
    flash_attn<<<dim3(16, BB*HH), 256, FA_SMEM>>>(
        Qh, Ql, Kh, Kl, Vth, Vtl, relb, x_mask, Fl, Oh, Ol);

    // 9-10) Fc weights; X1 = x + O @ Fc^T (fp32)
    effw_split<<<4096, 256>>>(fc_W, fc_A, fc_B, fWh, fWl, DD, (long long)DD*DD);
    tc_gemm<128,0><<<dim3(8,32,1), 256, SMEM128>>>(
        Oh, Ol, fWh, fWl, X1, x, nullptr, nullptr,
        DD, DD, DD, DD, 1, 0,0, 0,0, 0,0);

    // 11) RMSNorm 3 -> split Y
    rms_split<<<BT, 256>>>(X1, norm3_w, Yh, Yl);

    // 12-13) W1 weights; fused W1 GEMM + GEGLU -> split G [B,T,2D]
    effw_split<<<16384,256>>>(w1_W, w1_A, w1_B, w1h, w1l, DD, (long long)4*DD*DD);
    tc_gemm<128,3><<<dim3(32,32,1), 256, SMEM128>>>(
        Yh, Yl, w1h, w1l, nullptr, nullptr, Gh, Gl,
        DD, DD, DD, 2*DD, 1, 0,0, 0,0, 0,0);

    // 14-15) W2 weights; out_x = X1 + G @ W2^T (fp32)
    effw_split<<<8192, 256>>>(w2_W, w2_A, w2_B, w2h, w2l, 2*DD, (long long)2*DD*DD);
    tc_gemm<128,0><<<dim3(8,32,1), 256, SMEM128>>>(
        Gh, Gl, w2h, w2l, outx, X1, nullptr, nullptr,
        2*DD, 2*DD, 2*DD, DD, 1, 0,0, 0,0, 0,0);

    // 16) positional bias output (independent)
    posbias_kernel<<<(TT*TT)/256, 256>>>(relb, outbias);
}